// round 2
// baseline (speedup 1.0000x reference)
#include <cuda_runtime.h>
#include <cstddef>

// Problem constants
#define B_  2
#define S_  1024
#define HID_ 2048
#define NH_ 16
#define HD_ 128
#define NN_ 16
#define RHID_ 1024
#define SCALE_ 0.08838834764831845f   // 128^-0.5

// Scratch (device globals: allocation-free per harness rules)
__device__ float g_q [B_ * S_ * NH_ * HD_];           // (b,s,h,d)  16.8 MB
__device__ float g_k [B_ * S_ * NN_ * NH_ * HD_];     // (b,s,n, neigh*HD) 268 MB
__device__ float g_v [B_ * S_ * NN_ * NH_ * HD_];     // 268 MB
__device__ float g_ao[B_ * S_ * NH_ * HD_];           // attention output 16.8 MB

// ---------------------------------------------------------------------------
// Tiled SGEMM: C = alpha * (A @ B) + (R ? R : 0)
// A: M x K row-major, B: K x N row-major, C/R: M x N row-major.
// BM=BN=128, BK=16, 256 threads, 8x8 microtile per thread.
// Requires M%128==0, N%128==0, K%16==0 (all true here).
// ---------------------------------------------------------------------------
#define BM 128
#define BN 128
#define BKK 16
#define TM 8
#define TN 8

__global__ __launch_bounds__(256) void sgemm_kernel(
    const float* __restrict__ A, const float* __restrict__ B,
    const float* __restrict__ R, float* __restrict__ C,
    int M, int N, int K, float alpha)
{
    __shared__ float As[BKK * (BM + 1)];   // +1 pad: conflict-free transposed store
    __shared__ float Bs[BKK * BN];

    const int tid = threadIdx.x;
    const int bm = blockIdx.y * BM;
    const int bn = blockIdx.x * BN;
    const int ty = tid >> 4;   // 0..15
    const int tx = tid & 15;   // 0..15

    float acc[TM][TN];
#pragma unroll
    for (int i = 0; i < TM; i++)
#pragma unroll
        for (int j = 0; j < TN; j++) acc[i][j] = 0.f;

    for (int k0 = 0; k0 < K; k0 += BKK) {
#pragma unroll
        for (int t = 0; t < 2; t++) {
            int l = tid + t * 256;
            // A tile: 128 rows x 16 cols, 4 float4 per row
            int ar = l >> 2;
            int ak = (l & 3) << 2;
            float4 av = *(const float4*)(A + (size_t)(bm + ar) * K + k0 + ak);
            As[(ak + 0) * (BM + 1) + ar] = av.x;
            As[(ak + 1) * (BM + 1) + ar] = av.y;
            As[(ak + 2) * (BM + 1) + ar] = av.z;
            As[(ak + 3) * (BM + 1) + ar] = av.w;
            // B tile: 16 rows x 128 cols, 32 float4 per row
            int br = l >> 5;
            int bc = (l & 31) << 2;
            float4 bv = *(const float4*)(B + (size_t)(k0 + br) * N + bn + bc);
            *(float4*)(Bs + br * BN + bc) = bv;
        }
        __syncthreads();

#pragma unroll
        for (int kk = 0; kk < BKK; kk++) {
            float a[TM], bf[TN];
#pragma unroll
            for (int i = 0; i < TM; i++) a[i] = As[kk * (BM + 1) + ty * TM + i];
            float4 b0 = *(float4*)(Bs + kk * BN + tx * TN);
            float4 b1 = *(float4*)(Bs + kk * BN + tx * TN + 4);
            bf[0] = b0.x; bf[1] = b0.y; bf[2] = b0.z; bf[3] = b0.w;
            bf[4] = b1.x; bf[5] = b1.y; bf[6] = b1.z; bf[7] = b1.w;
#pragma unroll
            for (int i = 0; i < TM; i++)
#pragma unroll
                for (int j = 0; j < TN; j++)
                    acc[i][j] = fmaf(a[i], bf[j], acc[i][j]);
        }
        __syncthreads();
    }

    // Epilogue: scale + optional residual, vectorized stores
#pragma unroll
    for (int i = 0; i < TM; i++) {
        size_t row = (size_t)(bm + ty * TM + i);
#pragma unroll
        for (int j = 0; j < TN; j += 4) {
            size_t idx = row * N + bn + tx * TN + j;
            float4 v;
            v.x = acc[i][j + 0] * alpha;
            v.y = acc[i][j + 1] * alpha;
            v.z = acc[i][j + 2] * alpha;
            v.w = acc[i][j + 3] * alpha;
            if (R) {
                float4 r = *(const float4*)(R + idx);
                v.x += r.x; v.y += r.y; v.z += r.z; v.w += r.w;
            }
            *(float4*)(C + idx) = v;
        }
    }
}

// ---------------------------------------------------------------------------
// Attention: per (b, s, h) block of 128 threads.
// 32 keys: i in [0,16) -> pos max(s-1,0), neighbor i
//          i in [16,32) -> pos s,          neighbor i-16
// scores via warp-cooperative float4 dot + shfl reduce; softmax in smem;
// output: thread d accumulates sum_i p[i]*v[i][d] (coalesced).
// ---------------------------------------------------------------------------
__global__ __launch_bounds__(128) void attn_kernel(
    const float* __restrict__ qb, const float* __restrict__ kb,
    const float* __restrict__ vb, float* __restrict__ ob)
{
    const int h = blockIdx.x;     // 0..15 (head == NN index)
    const int s = blockIdx.y;     // 0..1023
    const int b = blockIdx.z;     // 0..1
    const int tid = threadIdx.x;  // 0..127
    const int lane = tid & 31;
    const int w = tid >> 5;

    __shared__ float sc[32];
    __shared__ float pr[32];

    const float* qv = qb + ((size_t)(b * S_ + s) * NH_ + h) * HD_;
    const float4 q4 = ((const float4*)qv)[lane];

    const int pprev = (s > 0) ? (s - 1) : 0;

#pragma unroll
    for (int j = 0; j < 8; j++) {
        int i = w * 8 + j;
        int p = (i < 16) ? pprev : s;
        int n = i & 15;
        const float* kr = kb + ((size_t)((b * S_ + p) * NN_ + h)) * (NH_ * HD_) + n * HD_;
        float4 k4 = ((const float4*)kr)[lane];
        float part = q4.x * k4.x + q4.y * k4.y + q4.z * k4.z + q4.w * k4.w;
#pragma unroll
        for (int off = 16; off; off >>= 1)
            part += __shfl_xor_sync(0xffffffffu, part, off);
        if (lane == 0) sc[i] = part;
    }
    __syncthreads();

    if (tid < 32) {
        float x = sc[tid];
        float m = x;
#pragma unroll
        for (int off = 16; off; off >>= 1)
            m = fmaxf(m, __shfl_xor_sync(0xffffffffu, m, off));
        float e = expf(x - m);
        float sum = e;
#pragma unroll
        for (int off = 16; off; off >>= 1)
            sum += __shfl_xor_sync(0xffffffffu, sum, off);
        pr[tid] = e / sum;
    }
    __syncthreads();

    float acc = 0.f;
    const int d = tid;
#pragma unroll 8
    for (int i = 0; i < 32; i++) {
        int p = (i < 16) ? pprev : s;
        int n = i & 15;
        acc += pr[i] * vb[((size_t)((b * S_ + p) * NN_ + h)) * (NH_ * HD_) + n * HD_ + d];
    }
    ob[((size_t)(b * S_ + s) * NH_ + h) * HD_ + d] = acc;
}

// ---------------------------------------------------------------------------
// Launch
// ---------------------------------------------------------------------------
extern "C" void kernel_launch(void* const* d_in, const int* in_sizes, int n_in,
                              void* d_out, int out_size)
{
    const float* hidden = (const float*)d_in[0];  // (B,S,HID)
    const float* ext    = (const float*)d_in[1];  // (B,S,NN,RHID)
    const float* Wq     = (const float*)d_in[2];  // (HID, NH*HD)
    const float* Wk     = (const float*)d_in[3];  // (RHID, NH*HD)
    const float* Wv     = (const float*)d_in[4];  // (RHID, NH*HD)
    const float* Wo     = (const float*)d_in[5];  // (NH*HD, HID)
    float* out = (float*)d_out;

    float *q, *k, *v, *ao;
    cudaGetSymbolAddress((void**)&q,  g_q);
    cudaGetSymbolAddress((void**)&k,  g_k);
    cudaGetSymbolAddress((void**)&v,  g_v);
    cudaGetSymbolAddress((void**)&ao, g_ao);

    const int MQ = B_ * S_;        // 2048
    const int MK = B_ * S_ * NN_;  // 32768
    const int NOUT = NH_ * HD_;    // 2048

    dim3 blk(256);
    // Q = hidden @ Wq * SCALE
    sgemm_kernel<<<dim3(NOUT / BN, MQ / BM), blk>>>(hidden, Wq, nullptr, q,
                                                    MQ, NOUT, HID_, SCALE_);
    // K = ext @ Wk
    sgemm_kernel<<<dim3(NOUT / BN, MK / BM), blk>>>(ext, Wk, nullptr, k,
                                                    MK, NOUT, RHID_, 1.0f);
    // V = ext @ Wv
    sgemm_kernel<<<dim3(NOUT / BN, MK / BM), blk>>>(ext, Wv, nullptr, v,
                                                    MK, NOUT, RHID_, 1.0f);
    // Attention
    attn_kernel<<<dim3(NH_, S_, B_), dim3(128)>>>(q, k, v, ao);
    // out = ao @ Wo + hidden
    sgemm_kernel<<<dim3(HID_ / BN, MQ / BM), blk>>>(ao, Wo, hidden, out,
                                                    MQ, HID_, NOUT, 1.0f);
}

// round 3
// speedup vs baseline: 1.0025x; 1.0025x over previous
#include <cuda_runtime.h>
#include <cstddef>

// Problem constants
#define B_  2
#define S_  1024
#define HID_ 2048
#define NH_ 16
#define HD_ 128
#define NN_ 16
#define RHID_ 1024
#define SCALE_ 0.08838834764831845f   // 128^-0.5

// Scratch (device globals: allocation-free per harness rules)
__device__ float g_q [B_ * S_ * NH_ * HD_];           // (b,s,h,d)  16.8 MB
__device__ float g_k [B_ * S_ * NN_ * NH_ * HD_];     // (b,s,n, neigh*HD) 268 MB
__device__ float g_v [B_ * S_ * NN_ * NH_ * HD_];     // 268 MB
__device__ float g_ao[B_ * S_ * NH_ * HD_];           // attention output 16.8 MB

// ---------------------------------------------------------------------------
// Tiled SGEMM: C = alpha * (A @ B) + (R ? R : 0)
// A: M x K row-major, B: K x N row-major, C/R: M x N row-major.
// BM=BN=128, BK=16, 256 threads, 8x8 microtile per thread.
// Requires M%128==0, N%128==0, K%16==0 (all true here).
// ---------------------------------------------------------------------------
#define BM 128
#define BN 128
#define BKK 16
#define TM 8
#define TN 8

__global__ __launch_bounds__(256) void sgemm_kernel(
    const float* __restrict__ A, const float* __restrict__ B,
    const float* __restrict__ R, float* __restrict__ C,
    int M, int N, int K, float alpha)
{
    __shared__ float As[BKK * (BM + 1)];   // +1 pad: conflict-free transposed store
    __shared__ float Bs[BKK * BN];

    const int tid = threadIdx.x;
    const int bm = blockIdx.y * BM;
    const int bn = blockIdx.x * BN;
    const int ty = tid >> 4;   // 0..15
    const int tx = tid & 15;   // 0..15

    float acc[TM][TN];
#pragma unroll
    for (int i = 0; i < TM; i++)
#pragma unroll
        for (int j = 0; j < TN; j++) acc[i][j] = 0.f;

    for (int k0 = 0; k0 < K; k0 += BKK) {
#pragma unroll
        for (int t = 0; t < 2; t++) {
            int l = tid + t * 256;
            // A tile: 128 rows x 16 cols, 4 float4 per row
            int ar = l >> 2;
            int ak = (l & 3) << 2;
            float4 av = *(const float4*)(A + (size_t)(bm + ar) * K + k0 + ak);
            As[(ak + 0) * (BM + 1) + ar] = av.x;
            As[(ak + 1) * (BM + 1) + ar] = av.y;
            As[(ak + 2) * (BM + 1) + ar] = av.z;
            As[(ak + 3) * (BM + 1) + ar] = av.w;
            // B tile: 16 rows x 128 cols, 32 float4 per row
            int br = l >> 5;
            int bc = (l & 31) << 2;
            float4 bv = *(const float4*)(B + (size_t)(k0 + br) * N + bn + bc);
            *(float4*)(Bs + br * BN + bc) = bv;
        }
        __syncthreads();

#pragma unroll
        for (int kk = 0; kk < BKK; kk++) {
            float a[TM], bf[TN];
#pragma unroll
            for (int i = 0; i < TM; i++) a[i] = As[kk * (BM + 1) + ty * TM + i];
            float4 b0 = *(float4*)(Bs + kk * BN + tx * TN);
            float4 b1 = *(float4*)(Bs + kk * BN + tx * TN + 4);
            bf[0] = b0.x; bf[1] = b0.y; bf[2] = b0.z; bf[3] = b0.w;
            bf[4] = b1.x; bf[5] = b1.y; bf[6] = b1.z; bf[7] = b1.w;
#pragma unroll
            for (int i = 0; i < TM; i++)
#pragma unroll
                for (int j = 0; j < TN; j++)
                    acc[i][j] = fmaf(a[i], bf[j], acc[i][j]);
        }
        __syncthreads();
    }

    // Epilogue: scale + optional residual, vectorized stores
#pragma unroll
    for (int i = 0; i < TM; i++) {
        size_t row = (size_t)(bm + ty * TM + i);
#pragma unroll
        for (int j = 0; j < TN; j += 4) {
            size_t idx = row * N + bn + tx * TN + j;
            float4 v;
            v.x = acc[i][j + 0] * alpha;
            v.y = acc[i][j + 1] * alpha;
            v.z = acc[i][j + 2] * alpha;
            v.w = acc[i][j + 3] * alpha;
            if (R) {
                float4 r = *(const float4*)(R + idx);
                v.x += r.x; v.y += r.y; v.z += r.z; v.w += r.w;
            }
            *(float4*)(C + idx) = v;
        }
    }
}

// ---------------------------------------------------------------------------
// Attention: per (b, s, h) block of 128 threads.
// 32 keys: i in [0,16) -> pos max(s-1,0), neighbor i
//          i in [16,32) -> pos s,          neighbor i-16
// scores via warp-cooperative float4 dot + shfl reduce; softmax in smem;
// output: thread d accumulates sum_i p[i]*v[i][d] (coalesced).
// ---------------------------------------------------------------------------
__global__ __launch_bounds__(128) void attn_kernel(
    const float* __restrict__ qb, const float* __restrict__ kb,
    const float* __restrict__ vb, float* __restrict__ ob)
{
    const int h = blockIdx.x;     // 0..15 (head == NN index)
    const int s = blockIdx.y;     // 0..1023
    const int b = blockIdx.z;     // 0..1
    const int tid = threadIdx.x;  // 0..127
    const int lane = tid & 31;
    const int w = tid >> 5;

    __shared__ float sc[32];
    __shared__ float pr[32];

    const float* qv = qb + ((size_t)(b * S_ + s) * NH_ + h) * HD_;
    const float4 q4 = ((const float4*)qv)[lane];

    const int pprev = (s > 0) ? (s - 1) : 0;

#pragma unroll
    for (int j = 0; j < 8; j++) {
        int i = w * 8 + j;
        int p = (i < 16) ? pprev : s;
        int n = i & 15;
        const float* kr = kb + ((size_t)((b * S_ + p) * NN_ + h)) * (NH_ * HD_) + n * HD_;
        float4 k4 = ((const float4*)kr)[lane];
        float part = q4.x * k4.x + q4.y * k4.y + q4.z * k4.z + q4.w * k4.w;
#pragma unroll
        for (int off = 16; off; off >>= 1)
            part += __shfl_xor_sync(0xffffffffu, part, off);
        if (lane == 0) sc[i] = part;
    }
    __syncthreads();

    if (tid < 32) {
        float x = sc[tid];
        float m = x;
#pragma unroll
        for (int off = 16; off; off >>= 1)
            m = fmaxf(m, __shfl_xor_sync(0xffffffffu, m, off));
        float e = expf(x - m);
        float sum = e;
#pragma unroll
        for (int off = 16; off; off >>= 1)
            sum += __shfl_xor_sync(0xffffffffu, sum, off);
        pr[tid] = e / sum;
    }
    __syncthreads();

    float acc = 0.f;
    const int d = tid;
#pragma unroll 8
    for (int i = 0; i < 32; i++) {
        int p = (i < 16) ? pprev : s;
        int n = i & 15;
        acc += pr[i] * vb[((size_t)((b * S_ + p) * NN_ + h)) * (NH_ * HD_) + n * HD_ + d];
    }
    ob[((size_t)(b * S_ + s) * NH_ + h) * HD_ + d] = acc;
}

// ---------------------------------------------------------------------------
// Launch
// ---------------------------------------------------------------------------
extern "C" void kernel_launch(void* const* d_in, const int* in_sizes, int n_in,
                              void* d_out, int out_size)
{
    const float* hidden = (const float*)d_in[0];  // (B,S,HID)
    const float* ext    = (const float*)d_in[1];  // (B,S,NN,RHID)
    const float* Wq     = (const float*)d_in[2];  // (HID, NH*HD)
    const float* Wk     = (const float*)d_in[3];  // (RHID, NH*HD)
    const float* Wv     = (const float*)d_in[4];  // (RHID, NH*HD)
    const float* Wo     = (const float*)d_in[5];  // (NH*HD, HID)
    float* out = (float*)d_out;

    float *q, *k, *v, *ao;
    cudaGetSymbolAddress((void**)&q,  g_q);
    cudaGetSymbolAddress((void**)&k,  g_k);
    cudaGetSymbolAddress((void**)&v,  g_v);
    cudaGetSymbolAddress((void**)&ao, g_ao);

    const int MQ = B_ * S_;        // 2048
    const int MK = B_ * S_ * NN_;  // 32768
    const int NOUT = NH_ * HD_;    // 2048

    dim3 blk(256);
    // Q = hidden @ Wq * SCALE
    sgemm_kernel<<<dim3(NOUT / BN, MQ / BM), blk>>>(hidden, Wq, nullptr, q,
                                                    MQ, NOUT, HID_, SCALE_);
    // K = ext @ Wk
    sgemm_kernel<<<dim3(NOUT / BN, MK / BM), blk>>>(ext, Wk, nullptr, k,
                                                    MK, NOUT, RHID_, 1.0f);
    // V = ext @ Wv
    sgemm_kernel<<<dim3(NOUT / BN, MK / BM), blk>>>(ext, Wv, nullptr, v,
                                                    MK, NOUT, RHID_, 1.0f);
    // Attention
    attn_kernel<<<dim3(NH_, S_, B_), dim3(128)>>>(q, k, v, ao);
    // out = ao @ Wo + hidden
    sgemm_kernel<<<dim3(HID_ / BN, MQ / BM), blk>>>(ao, Wo, hidden, out,
                                                    MQ, HID_, NOUT, 1.0f);
}

// round 5
// speedup vs baseline: 2.7739x; 2.7669x over previous
#include <cuda_runtime.h>
#include <cuda_bf16.h>
#include <cstdint>
#include <cstddef>

// Problem constants
#define B_   2
#define S_   1024
#define HID_ 2048
#define NH_  16
#define HD_  128
#define NN_  16
#define RHID_ 1024
#define SCALE_ 0.08838834764831845f   // 128^-0.5

// ---------------------------------------------------------------------------
// Scratch (device globals: allocation-free per harness rules)
// ---------------------------------------------------------------------------
__device__ float g_q [4194304];     // (B*S, 2048) fp32
__device__ float g_k [67108864];    // (B*S*NN, 2048) fp32
__device__ float g_v [67108864];
__device__ float g_ao[4194304];

__device__ __nv_bfloat16 g_exth[33554432], g_extl[33554432];  // ext split
__device__ __nv_bfloat16 g_hidh[4194304],  g_hidl[4194304];   // hidden split
__device__ __nv_bfloat16 g_aoh [4194304],  g_aol [4194304];   // attn-out split
__device__ __nv_bfloat16 g_wqh [4194304],  g_wql [4194304];   // Wq^T split (N x K)
__device__ __nv_bfloat16 g_wkh [2097152],  g_wkl [2097152];   // Wk^T
__device__ __nv_bfloat16 g_wvh [2097152],  g_wvl [2097152];   // Wv^T
__device__ __nv_bfloat16 g_woh [4194304],  g_wol [4194304];   // Wo^T

// ---------------------------------------------------------------------------
// PTX helpers (compute_103-safe: cp.async + ldmatrix + mma.sync only)
// ---------------------------------------------------------------------------
__device__ __forceinline__ void cp16(uint32_t dst, const void* src) {
    asm volatile("cp.async.cg.shared.global [%0], [%1], 16;"
                 :: "r"(dst), "l"(src) : "memory");
}

__device__ __forceinline__ void ldsm4(uint32_t* r, uint32_t a) {
    asm volatile("ldmatrix.sync.aligned.m8n8.x4.shared.b16 {%0,%1,%2,%3}, [%4];"
                 : "=r"(r[0]), "=r"(r[1]), "=r"(r[2]), "=r"(r[3]) : "r"(a));
}

__device__ __forceinline__ void mma_bf16(float* c, const uint32_t* a,
                                         const uint32_t* b) {
    asm volatile(
        "mma.sync.aligned.m16n8k16.row.col.f32.bf16.bf16.f32 "
        "{%0,%1,%2,%3}, {%4,%5,%6,%7}, {%8,%9}, {%0,%1,%2,%3};"
        : "+f"(c[0]), "+f"(c[1]), "+f"(c[2]), "+f"(c[3])
        : "r"(a[0]), "r"(a[1]), "r"(a[2]), "r"(a[3]), "r"(b[0]), "r"(b[1]));
}

// ---------------------------------------------------------------------------
// bf16x3-split tensor-core GEMM:  C[M,N] = alpha * A[M,K] @ Bt[N,K]^T (+ R)
// A row-major (M,K) hi/lo bf16; Bt row-major (N,K) hi/lo bf16.
// CTA tile 128x128, BK=32, 256 threads (8 warps, 4x2), warp tile 32x64.
// SMEM rows padded to 40 bf16 (80B) -> conflict-free ldmatrix.
// Per stage: Ah|Al|Bh|Bl tiles, 10240B each = 40960B; double buffered.
// ---------------------------------------------------------------------------
#define GEMM_DSMEM 81920

__global__ __launch_bounds__(256) void gemm_mma_kernel(
    const __nv_bfloat16* __restrict__ Ah, const __nv_bfloat16* __restrict__ Al,
    const __nv_bfloat16* __restrict__ Bh, const __nv_bfloat16* __restrict__ Bl,
    const float* __restrict__ R, float* __restrict__ C,
    int Kdim, int Ndim, float alpha)
{
    extern __shared__ __nv_bfloat16 sm[];
    const int tid = threadIdx.x;
    const int lane = tid & 31;
    const int wid = tid >> 5;
    const int wm = wid & 3;        // 4 warp-rows (m)
    const int wn = wid >> 2;       // 2 warp-cols (n)
    const int bm = blockIdx.y * 128;
    const int bn = blockIdx.x * 128;
    const int nkb = Kdim >> 5;     // BK = 32

    const uint32_t smem_b = (uint32_t)__cvta_generic_to_shared(sm);

    float acc[2][8][4];
#pragma unroll
    for (int mt = 0; mt < 2; mt++)
#pragma unroll
        for (int nt = 0; nt < 8; nt++)
#pragma unroll
            for (int i = 0; i < 4; i++) acc[mt][nt][i] = 0.f;

    // cp.async stage load: 4 tiles x 128 rows x 4 16B-chunks = 2048 chunks,
    // 8 per thread.  tile order: 0=Ah 1=Al 2=Bh 3=Bl.
    auto load_stage = [&](int kb) {
        const uint32_t base = smem_b + (uint32_t)(kb & 1) * 40960u;
#pragma unroll
        for (int i = 0; i < 8; i++) {
            const int t = i >> 1;                 // compile-time tile id
            int cc = tid + (i & 1) * 256;         // 0..511 within tile
            int row = cc >> 2, u = cc & 3;
            const __nv_bfloat16* p =
                (t == 0 ? Ah : t == 1 ? Al : t == 2 ? Bh : Bl) +
                (size_t)((t < 2 ? bm : bn) + row) * Kdim + kb * 32 + u * 8;
            cp16(base + (uint32_t)t * 10240u + (uint32_t)row * 80u +
                 (uint32_t)u * 16u, p);
        }
        asm volatile("cp.async.commit_group;" ::: "memory");
    };

    load_stage(0);

    for (int kb = 0; kb < nkb; kb++) {
        if (kb + 1 < nkb) {
            load_stage(kb + 1);
            asm volatile("cp.async.wait_group 1;" ::: "memory");
        } else {
            asm volatile("cp.async.wait_group 0;" ::: "memory");
        }
        __syncthreads();

        const uint32_t sA  = smem_b + (uint32_t)(kb & 1) * 40960u;
        const uint32_t sAl = sA + 10240u;
        const uint32_t sBh = sA + 20480u;
        const uint32_t sBl = sA + 30720u;

#pragma unroll
        for (int ks = 0; ks < 2; ks++) {
            const int k0 = ks * 16;

            uint32_t ah[2][4], al[2][4];
#pragma unroll
            for (int mt = 0; mt < 2; mt++) {
                int row = wm * 32 + mt * 16 + (lane & 7) + 8 * ((lane >> 3) & 1);
                int col = k0 + 8 * (lane >> 4);
                uint32_t ad = (uint32_t)row * 80u + (uint32_t)col * 2u;
                ldsm4(ah[mt], sA  + ad);
                ldsm4(al[mt], sAl + ad);
            }

            uint32_t bh[8][2], bl[8][2];
#pragma unroll
            for (int np = 0; np < 4; np++) {      // x4 covers two n8 tiles
                int row = wn * 64 + np * 16 + (lane & 7) + 8 * (lane >> 4);
                int col = k0 + 8 * ((lane >> 3) & 1);
                uint32_t bd = (uint32_t)row * 80u + (uint32_t)col * 2u;
                uint32_t rh[4], rl[4];
                ldsm4(rh, sBh + bd);
                ldsm4(rl, sBl + bd);
                bh[2 * np][0] = rh[0]; bh[2 * np][1] = rh[1];
                bh[2 * np + 1][0] = rh[2]; bh[2 * np + 1][1] = rh[3];
                bl[2 * np][0] = rl[0]; bl[2 * np][1] = rl[1];
                bl[2 * np + 1][0] = rl[2]; bl[2 * np + 1][1] = rl[3];
            }

#pragma unroll
            for (int mt = 0; mt < 2; mt++)
#pragma unroll
                for (int nt = 0; nt < 8; nt++) {
                    mma_bf16(acc[mt][nt], ah[mt], bh[nt]);   // hi*hi
                    mma_bf16(acc[mt][nt], ah[mt], bl[nt]);   // hi*lo
                    mma_bf16(acc[mt][nt], al[mt], bh[nt]);   // lo*hi
                }
        }
        __syncthreads();
    }

    // Epilogue: fragment layout -> float2 stores (+alpha, +residual)
#pragma unroll
    for (int mt = 0; mt < 2; mt++) {
        int row0 = bm + wm * 32 + mt * 16 + (lane >> 2);
#pragma unroll
        for (int nt = 0; nt < 8; nt++) {
            int col = bn + wn * 64 + nt * 8 + 2 * (lane & 3);
            size_t i0 = (size_t)row0 * Ndim + col;
            size_t i1 = i0 + (size_t)8 * Ndim;
            float2 v0, v1;
            v0.x = acc[mt][nt][0] * alpha;
            v0.y = acc[mt][nt][1] * alpha;
            v1.x = acc[mt][nt][2] * alpha;
            v1.y = acc[mt][nt][3] * alpha;
            if (R) {
                const float2 r0 = *(const float2*)(R + i0);
                const float2 r1 = *(const float2*)(R + i1);
                v0.x += r0.x; v0.y += r0.y;
                v1.x += r1.x; v1.y += r1.y;
            }
            *(float2*)(C + i0) = v0;
            *(float2*)(C + i1) = v1;
        }
    }
}

// ---------------------------------------------------------------------------
// fp32 -> bf16 hi/lo split (elementwise, float4)
// ---------------------------------------------------------------------------
__global__ __launch_bounds__(256) void split_kernel(
    const float* __restrict__ x,
    __nv_bfloat16* __restrict__ hi, __nv_bfloat16* __restrict__ lo, int n4)
{
    int i = blockIdx.x * 256 + threadIdx.x;
    if (i >= n4) return;
    float4 v = ((const float4*)x)[i];
    __nv_bfloat16 h0 = __float2bfloat16(v.x);
    __nv_bfloat16 h1 = __float2bfloat16(v.y);
    __nv_bfloat16 h2 = __float2bfloat16(v.z);
    __nv_bfloat16 h3 = __float2bfloat16(v.w);
    __nv_bfloat16 l0 = __float2bfloat16(v.x - __bfloat162float(h0));
    __nv_bfloat16 l1 = __float2bfloat16(v.y - __bfloat162float(h1));
    __nv_bfloat16 l2 = __float2bfloat16(v.z - __bfloat162float(h2));
    __nv_bfloat16 l3 = __float2bfloat16(v.w - __bfloat162float(h3));
    __nv_bfloat162 ph0; ph0.x = h0; ph0.y = h1;
    __nv_bfloat162 ph1; ph1.x = h2; ph1.y = h3;
    __nv_bfloat162 pl0; pl0.x = l0; pl0.y = l1;
    __nv_bfloat162 pl1; pl1.x = l2; pl1.y = l3;
    ((__nv_bfloat162*)hi)[2 * i]     = ph0;
    ((__nv_bfloat162*)hi)[2 * i + 1] = ph1;
    ((__nv_bfloat162*)lo)[2 * i]     = pl0;
    ((__nv_bfloat162*)lo)[2 * i + 1] = pl1;
}

// ---------------------------------------------------------------------------
// Transpose + split: W (K x N fp32) -> Wt hi/lo (N x K bf16)
// ---------------------------------------------------------------------------
__global__ __launch_bounds__(256) void tsplit_kernel(
    const float* __restrict__ W,
    __nv_bfloat16* __restrict__ hi, __nv_bfloat16* __restrict__ lo, int K, int N)
{
    __shared__ float t[32][33];
    const int tx = threadIdx.x, ty = threadIdx.y;  // 32 x 8
    const int bn = blockIdx.x * 32;
    const int bk = blockIdx.y * 32;
#pragma unroll
    for (int r = 0; r < 4; r++)
        t[ty + r * 8][tx] = W[(size_t)(bk + ty + r * 8) * N + bn + tx];
    __syncthreads();
#pragma unroll
    for (int r = 0; r < 4; r++) {
        int row = ty + r * 8;
        float v = t[tx][row];
        __nv_bfloat16 h = __float2bfloat16(v);
        __nv_bfloat16 l = __float2bfloat16(v - __bfloat162float(h));
        size_t idx = (size_t)(bn + row) * K + bk + tx;
        hi[idx] = h;
        lo[idx] = l;
    }
}

// ---------------------------------------------------------------------------
// Attention (unchanged from passing R2 kernel; 111us)
// ---------------------------------------------------------------------------
__global__ __launch_bounds__(128) void attn_kernel(
    const float* __restrict__ qb, const float* __restrict__ kb,
    const float* __restrict__ vb, float* __restrict__ ob)
{
    const int h = blockIdx.x;
    const int s = blockIdx.y;
    const int b = blockIdx.z;
    const int tid = threadIdx.x;
    const int lane = tid & 31;
    const int w = tid >> 5;

    __shared__ float sc[32];
    __shared__ float pr[32];

    const float* qv = qb + ((size_t)(b * S_ + s) * NH_ + h) * HD_;
    const float4 q4 = ((const float4*)qv)[lane];

    const int pprev = (s > 0) ? (s - 1) : 0;

#pragma unroll
    for (int j = 0; j < 8; j++) {
        int i = w * 8 + j;
        int p = (i < 16) ? pprev : s;
        int n = i & 15;
        const float* kr = kb + ((size_t)((b * S_ + p) * NN_ + h)) * (NH_ * HD_) + n * HD_;
        float4 k4 = ((const float4*)kr)[lane];
        float part = q4.x * k4.x + q4.y * k4.y + q4.z * k4.z + q4.w * k4.w;
#pragma unroll
        for (int off = 16; off; off >>= 1)
            part += __shfl_xor_sync(0xffffffffu, part, off);
        if (lane == 0) sc[i] = part;
    }
    __syncthreads();

    if (tid < 32) {
        float x = sc[tid];
        float m = x;
#pragma unroll
        for (int off = 16; off; off >>= 1)
            m = fmaxf(m, __shfl_xor_sync(0xffffffffu, m, off));
        float e = expf(x - m);
        float sum = e;
#pragma unroll
        for (int off = 16; off; off >>= 1)
            sum += __shfl_xor_sync(0xffffffffu, sum, off);
        pr[tid] = e / sum;
    }
    __syncthreads();

    float acc = 0.f;
    const int d = tid;
#pragma unroll 8
    for (int i = 0; i < 32; i++) {
        int p = (i < 16) ? pprev : s;
        int n = i & 15;
        acc += pr[i] * vb[((size_t)((b * S_ + p) * NN_ + h)) * (NH_ * HD_) + n * HD_ + d];
    }
    ob[((size_t)(b * S_ + s) * NH_ + h) * HD_ + d] = acc;
}

// ---------------------------------------------------------------------------
// Launch
// ---------------------------------------------------------------------------
extern "C" void kernel_launch(void* const* d_in, const int* in_sizes, int n_in,
                              void* d_out, int out_size)
{
    const float* hidden = (const float*)d_in[0];  // (B,S,HID)
    const float* ext    = (const float*)d_in[1];  // (B,S,NN,RHID)
    const float* Wq     = (const float*)d_in[2];  // (HID, 2048)
    const float* Wk     = (const float*)d_in[3];  // (RHID, 2048)
    const float* Wv     = (const float*)d_in[4];  // (RHID, 2048)
    const float* Wo     = (const float*)d_in[5];  // (2048, HID)
    float* out = (float*)d_out;

    float *q, *k, *v, *ao;
    cudaGetSymbolAddress((void**)&q,  g_q);
    cudaGetSymbolAddress((void**)&k,  g_k);
    cudaGetSymbolAddress((void**)&v,  g_v);
    cudaGetSymbolAddress((void**)&ao, g_ao);
    __nv_bfloat16 *exth, *extl, *hidh, *hidl, *aoh, *aol;
    __nv_bfloat16 *wqh, *wql, *wkh, *wkl, *wvh, *wvl, *woh, *wol;
    cudaGetSymbolAddress((void**)&exth, g_exth);
    cudaGetSymbolAddress((void**)&extl, g_extl);
    cudaGetSymbolAddress((void**)&hidh, g_hidh);
    cudaGetSymbolAddress((void**)&hidl, g_hidl);
    cudaGetSymbolAddress((void**)&aoh,  g_aoh);
    cudaGetSymbolAddress((void**)&aol,  g_aol);
    cudaGetSymbolAddress((void**)&wqh,  g_wqh);
    cudaGetSymbolAddress((void**)&wql,  g_wql);
    cudaGetSymbolAddress((void**)&wkh,  g_wkh);
    cudaGetSymbolAddress((void**)&wkl,  g_wkl);
    cudaGetSymbolAddress((void**)&wvh,  g_wvh);
    cudaGetSymbolAddress((void**)&wvl,  g_wvl);
    cudaGetSymbolAddress((void**)&woh,  g_woh);
    cudaGetSymbolAddress((void**)&wol,  g_wol);

    cudaFuncSetAttribute(gemm_mma_kernel,
                         cudaFuncAttributeMaxDynamicSharedMemorySize, GEMM_DSMEM);

    // Splits
    split_kernel<<<4096, 256>>>(hidden, hidh, hidl, 1048576);
    split_kernel<<<32768, 256>>>(ext, exth, extl, 8388608);
    // Weight transpose+split (W^T stored N x K)
    tsplit_kernel<<<dim3(64, 64), dim3(32, 8)>>>(Wq, wqh, wql, 2048, 2048);
    tsplit_kernel<<<dim3(64, 32), dim3(32, 8)>>>(Wk, wkh, wkl, 1024, 2048);
    tsplit_kernel<<<dim3(64, 32), dim3(32, 8)>>>(Wv, wvh, wvl, 1024, 2048);
    tsplit_kernel<<<dim3(64, 64), dim3(32, 8)>>>(Wo, woh, wol, 2048, 2048);

    // Q = hidden @ Wq * SCALE            (M=2048, N=2048, K=2048)
    gemm_mma_kernel<<<dim3(16, 16), 256, GEMM_DSMEM>>>(
        hidh, hidl, wqh, wql, nullptr, q, 2048, 2048, SCALE_);
    // K = ext @ Wk                       (M=32768, N=2048, K=1024)
    gemm_mma_kernel<<<dim3(16, 256), 256, GEMM_DSMEM>>>(
        exth, extl, wkh, wkl, nullptr, k, 1024, 2048, 1.0f);
    // V = ext @ Wv
    gemm_mma_kernel<<<dim3(16, 256), 256, GEMM_DSMEM>>>(
        exth, extl, wvh, wvl, nullptr, v, 1024, 2048, 1.0f);

    // Attention
    attn_kernel<<<dim3(NH_, S_, B_), dim3(128)>>>(q, k, v, ao);

    // out = ao @ Wo + hidden
    split_kernel<<<4096, 256>>>(ao, aoh, aol, 1048576);
    gemm_mma_kernel<<<dim3(16, 16), 256, GEMM_DSMEM>>>(
        aoh, aol, woh, wol, hidden, out, 2048, 2048, 1.0f);
}